// round 10
// baseline (speedup 1.0000x reference)
#include <cuda_runtime.h>
#include <cstdint>

// 512 rows per 256-thread block, 2 rows/thread. 18 KB in-buffer (cp.async.cg,
// L1-bypass) + separate 6 KB out-buffer -> only 2 block barriers per tile.
// 24 KB smem, <=32 regs -> 8 CTAs/SM. All smem ops 64/128-bit, conflict-free.

constexpr int TPB = 256;
constexpr int RPB = 512;                  // rows per block
constexpr int IN4 = RPB * 9 / 4;          // 1152 float4 = 18 KB
constexpr int OUT4 = RPB * 3 / 4;         // 384 float4 = 6 KB

__device__ __forceinline__ void process_row(const float* __restrict__ x,
                                            float* __restrict__ o)
{
    int mi[3];
#pragma unroll
    for (int j = 0; j < 3; j++) {
        float a0 = x[3*j], a1 = x[3*j+1], a2 = x[3*j+2];
        bool q0 = (a0 > a1) && (a0 > a2);
        bool q2 = (a2 > a0) && (a2 > a1);
        mi[j] = (int)q0 - (int)q2;
    }
    int calc = ((mi[1] < 0) ? -mi[1] : mi[1]) * (mi[0] + mi[1] + mi[2]);
    int sc   = (calc > 0) - (calc < 0);

    float m[9];
#pragma unroll
    for (int j = 0; j < 3; j++) {
        bool keep = (mi[j] == sc);
#pragma unroll
        for (int k = 0; k < 3; k++)
            m[3*j + k] = keep ? x[3*j + k] : 0.0f;
    }
    float v0, v1, v2;
    if (sc == 0)      { v0 = m[1]; v1 = m[4]; v2 = m[7]; }
    else if (sc > 0)  { v0 = m[0]; v1 = m[3]; v2 = m[6]; }
    else              { v0 = m[2]; v1 = m[5]; v2 = m[8]; }

    bool b1 = (v1 > v0);
    float best01 = b1 ? v1 : v0;
    bool b2 = (v2 > best01);
#pragma unroll
    for (int k = 0; k < 3; k++) {
        float t01 = b1 ? m[3 + k] : m[k];
        o[k] = b2 ? m[6 + k] : t01;
    }
}

__global__ void __launch_bounds__(TPB, 8) concat_r2b(
    const float4* __restrict__ in4, float4* __restrict__ out4)
{
    __shared__ float4 s_in[IN4];          // 18 KB
    __shared__ float4 s_out[OUT4];        // 6 KB (separate: no reuse barrier)
    float2* si2 = reinterpret_cast<float2*>(s_in);
    float2* so2 = reinterpret_cast<float2*>(s_out);

    const int tid = threadIdx.x;
    const size_t base = (size_t)blockIdx.x * IN4;

    // Stage 1152 float4 via cp.async.cg: partial round first, then 4 full
    if (tid < IN4 - 4 * TPB) {            // 128 threads
        uint32_t dst = (uint32_t)__cvta_generic_to_shared(&s_in[4 * TPB + tid]);
        const float4* src = in4 + base + 4 * TPB + tid;
        asm volatile("cp.async.cg.shared.global [%0], [%1], 16;"
                     :: "r"(dst), "l"(src) : "memory");
    }
#pragma unroll
    for (int i = 0; i < 4; i++) {
        uint32_t dst = (uint32_t)__cvta_generic_to_shared(&s_in[i * TPB + tid]);
        const float4* src = in4 + base + i * TPB + tid;
        asm volatile("cp.async.cg.shared.global [%0], [%1], 16;"
                     :: "r"(dst), "l"(src) : "memory");
    }
    asm volatile("cp.async.commit_group;" ::: "memory");
    asm volatile("cp.async.wait_group 0;" ::: "memory");
    __syncthreads();

    // 2 rows = 18 floats = 9 LDS.64 at 72B lane stride (conflict-free)
    float x[18];
#pragma unroll
    for (int k = 0; k < 9; k++) {
        float2 v = si2[tid * 9 + k];
        x[2*k+0] = v.x; x[2*k+1] = v.y;
    }

    float o[6];
    process_row(x, o);
    process_row(x + 9, o + 3);

    // 6 floats = 3 STS.64 at 24B lane stride (conflict-free)
#pragma unroll
    for (int k = 0; k < 3; k++) {
        float2 v; v.x = o[2*k]; v.y = o[2*k+1];
        so2[tid * 3 + k] = v;
    }
    __syncthreads();

    // Coalesced streaming output: 384 float4 (256 + 128)
    const size_t obase = (size_t)blockIdx.x * OUT4;
    __stcs(&out4[obase + tid], s_out[tid]);
    if (tid < OUT4 - TPB)
        __stcs(&out4[obase + TPB + tid], s_out[TPB + tid]);
}

// Scalar tail for n_rows % 512 != 0 (not hit for N = 2^23)
__global__ void concat_tail(const float* __restrict__ in,
                            float* __restrict__ out,
                            int row_start, int n_rows)
{
    int row = row_start + blockIdx.x * blockDim.x + threadIdx.x;
    if (row >= n_rows) return;
    float x[9];
#pragma unroll
    for (int k = 0; k < 9; k++) x[k] = in[(size_t)row * 9 + k];
    float o[3];
    process_row(x, o);
#pragma unroll
    for (int k = 0; k < 3; k++) out[(size_t)row * 3 + k] = o[k];
}

extern "C" void kernel_launch(void* const* d_in, const int* in_sizes, int n_in,
                              void* d_out, int out_size)
{
    const float* in = (const float*)d_in[0];
    float* out = (float*)d_out;
    int n_rows = in_sizes[0] / 9;

    int nfull = n_rows / RPB;
    if (nfull > 0)
        concat_r2b<<<nfull, TPB>>>((const float4*)in, (float4*)out);

    int done = nfull * RPB;
    int rem = n_rows - done;
    if (rem > 0) {
        int grid = (rem + 255) / 256;
        concat_tail<<<grid, 256>>>(in, out, done, n_rows);
    }
}

// round 11
// speedup vs baseline: 1.0021x; 1.0021x over previous
#include <cuda_runtime.h>
#include <cstdint>

// Warp-autonomous convoys: TPB=128, each warp owns 64 contiguous rows
// (2 rows/thread). Each warp cp.asyncs its own 2304B region, waits its own
// group, computes, restages output in-place, stores — only __syncwarp, no
// block barriers. 9KB smem, <=32 regs -> 16 CTAs/SM = 64 independent
// warp-pipelines per SM at 100% occupancy.

constexpr int TPB = 128;                  // 4 warps
constexpr int RPW = 64;                   // rows per warp
constexpr int RPB = 256;                  // rows per block
constexpr int IN4_W = RPW * 9 / 4;        // 144 float4 per warp
constexpr int IN4_B = 4 * IN4_W;          // 576 float4 = 9216 B
constexpr int OUT4_W = RPW * 3 / 4;       // 48 float4 per warp

__device__ __forceinline__ void process_row(const float* __restrict__ x,
                                            float* __restrict__ o)
{
    int mi[3];
#pragma unroll
    for (int j = 0; j < 3; j++) {
        float a0 = x[3*j], a1 = x[3*j+1], a2 = x[3*j+2];
        bool q0 = (a0 > a1) && (a0 > a2);
        bool q2 = (a2 > a0) && (a2 > a1);
        mi[j] = (int)q0 - (int)q2;
    }
    int calc = ((mi[1] < 0) ? -mi[1] : mi[1]) * (mi[0] + mi[1] + mi[2]);
    int sc   = (calc > 0) - (calc < 0);

    float m[9];
#pragma unroll
    for (int j = 0; j < 3; j++) {
        bool keep = (mi[j] == sc);
#pragma unroll
        for (int k = 0; k < 3; k++)
            m[3*j + k] = keep ? x[3*j + k] : 0.0f;
    }
    float v0, v1, v2;
    if (sc == 0)      { v0 = m[1]; v1 = m[4]; v2 = m[7]; }
    else if (sc > 0)  { v0 = m[0]; v1 = m[3]; v2 = m[6]; }
    else              { v0 = m[2]; v1 = m[5]; v2 = m[8]; }

    bool b1 = (v1 > v0);
    float best01 = b1 ? v1 : v0;
    bool b2 = (v2 > best01);
#pragma unroll
    for (int k = 0; k < 3; k++) {
        float t01 = b1 ? m[3 + k] : m[k];
        o[k] = b2 ? m[6 + k] : t01;
    }
}

__global__ void __launch_bounds__(TPB, 16) concat_warp(
    const float4* __restrict__ in4, float4* __restrict__ out4)
{
    __shared__ float4 s[IN4_B];           // 9216 B, per-warp regions, reused

    const int lane = threadIdx.x & 31;
    const int w    = threadIdx.x >> 5;

    float4* sw  = s + w * IN4_W;                       // this warp's region
    float2* sw2 = reinterpret_cast<float2*>(sw);
    const size_t ibase = (size_t)blockIdx.x * IN4_B + w * IN4_W;

    // Warp-local staging: 144 float4 = 4 full rounds + 16-lane half round
#pragma unroll
    for (int i = 0; i < 4; i++) {
        uint32_t dst = (uint32_t)__cvta_generic_to_shared(&sw[i * 32 + lane]);
        const float4* src = in4 + ibase + i * 32 + lane;
        asm volatile("cp.async.cg.shared.global [%0], [%1], 16;"
                     :: "r"(dst), "l"(src) : "memory");
    }
    if (lane < IN4_W - 128) {             // 16 lanes
        uint32_t dst = (uint32_t)__cvta_generic_to_shared(&sw[128 + lane]);
        const float4* src = in4 + ibase + 128 + lane;
        asm volatile("cp.async.cg.shared.global [%0], [%1], 16;"
                     :: "r"(dst), "l"(src) : "memory");
    }
    asm volatile("cp.async.commit_group;" ::: "memory");
    asm volatile("cp.async.wait_group 0;" ::: "memory");
    __syncwarp();

    // 2 rows = 9 LDS.64 @ 72B lane stride (conflict-free per 16-lane phase)
    float x[18];
#pragma unroll
    for (int k = 0; k < 9; k++) {
        float2 v = sw2[lane * 9 + k];
        x[2*k+0] = v.x; x[2*k+1] = v.y;
    }
    __syncwarp();                         // warp's reads done before reuse

    float o[6];
    process_row(x, o);
    process_row(x + 9, o + 3);

    // Restage output in-place: 3 STS.64 @ 24B stride (conflict-free)
#pragma unroll
    for (int k = 0; k < 3; k++) {
        float2 v; v.x = o[2*k]; v.y = o[2*k+1];
        sw2[lane * 3 + k] = v;
    }
    __syncwarp();

    // Warp-local coalesced store: 48 float4 (1 full + 16-lane half round)
    const size_t obase = (size_t)blockIdx.x * (4 * OUT4_W) + w * OUT4_W;
    __stcs(&out4[obase + lane], sw[lane]);
    if (lane < OUT4_W - 32)               // 16 lanes
        __stcs(&out4[obase + 32 + lane], sw[32 + lane]);
}

// Scalar tail for n_rows % 256 != 0 (not hit for N = 2^23)
__global__ void concat_tail(const float* __restrict__ in,
                            float* __restrict__ out,
                            int row_start, int n_rows)
{
    int row = row_start + blockIdx.x * blockDim.x + threadIdx.x;
    if (row >= n_rows) return;
    float x[9];
#pragma unroll
    for (int k = 0; k < 9; k++) x[k] = in[(size_t)row * 9 + k];
    float o[3];
    process_row(x, o);
#pragma unroll
    for (int k = 0; k < 3; k++) out[(size_t)row * 3 + k] = o[k];
}

extern "C" void kernel_launch(void* const* d_in, const int* in_sizes, int n_in,
                              void* d_out, int out_size)
{
    const float* in = (const float*)d_in[0];
    float* out = (float*)d_out;
    int n_rows = in_sizes[0] / 9;

    int nfull = n_rows / RPB;
    if (nfull > 0)
        concat_warp<<<nfull, TPB>>>((const float4*)in, (float4*)out);

    int done = nfull * RPB;
    int rem = n_rows - done;
    if (rem > 0) {
        int grid = (rem + 255) / 256;
        concat_tail<<<grid, 256>>>(in, out, done, n_rows);
    }
}